// round 13
// baseline (speedup 1.0000x reference)
#include <cuda_runtime.h>
#include <cuda_fp16.h>
#include <cstdint>
#include <cfloat>

// VQ R13: single-pass fp16 screen with register top-2 certification.
// Each thread tracks (best, bestk, snd) over its 64-code slice per row.
// After global approx-max: rescore best exactly if >= thr; if snd also >= thr
// (rare), exact-rescan the whole slice. No score buffer, no recompute pass.

#define D    64
#define K    512
#define MT   128     // pixels per CTA
#define T    256     // threads per CTA (8 warps), 2 CTAs/SM
#define SXS  140     // padded sx row stride (floats): conflict-free frag loads

// SMEM layout (bytes) — ~103KB => 2 CTAs/SM
#define SX_OFF    0                       // x tile fp32 [d][SXS]        35840
#define BA_OFF    35840                   // codebook hi fp16 [512][128] 65536
#define SHES_OFF  101376                  // 512 f32                      2048
#define SAPX_OFF  103424                  // 128 u32 ordered approx-max    512
#define SBEST_OFF 103936                  // 128 u64 exact best           1024
#define SMEM_SZ   104960

__device__ __half g_ea[K * D];   // fp16 hi split, permuted+swizzled rows
__device__ float  g_hes[K];      // 0.5*||e||^2
__device__ int    g_mhbits = 0;  // max hes as int bits

// ---------------- helpers ----------------
__device__ __forceinline__ uint32_t smem_u32(const void* p) {
    uint32_t a;
    asm("{ .reg .u64 t; cvta.to.shared.u64 t, %1; cvt.u32.u64 %0, t; }" : "=r"(a) : "l"(p));
    return a;
}
#define MMA_F16(c, a0, a1, a2, a3, b0, b1)                                       \
    asm volatile("mma.sync.aligned.m16n8k16.row.col.f32.f16.f16.f32 "            \
        "{%0,%1,%2,%3},{%4,%5,%6,%7},{%8,%9},{%0,%1,%2,%3};"                     \
        : "+f"((c)[0]), "+f"((c)[1]), "+f"((c)[2]), "+f"((c)[3])                  \
        : "r"(a0), "r"(a1), "r"(a2), "r"(a3), "r"(b0), "r"(b1))

__device__ __forceinline__ void cp16(uint32_t dst, const void* src) {
    asm volatile("cp.async.cg.shared.global [%0], [%1], 16;" :: "r"(dst), "l"(src) : "memory");
}
#define CP_COMMIT() asm volatile("cp.async.commit_group;" ::: "memory")
#define CP_WAIT(n)  asm volatile("cp.async.wait_group %0;" :: "n"(n) : "memory")

__device__ __forceinline__ uint32_t pack2(__half x, __half y) {
    __half2 h = __halves2half2(x, y);
    return *(uint32_t*)&h;
}
__device__ __forceinline__ unsigned ord_enc(float f) {
    unsigned u = __float_as_uint(f);
    return (u & 0x80000000u) ? ~u : (u | 0x80000000u);
}

// exact fp32 rescore: x_p . e_k - 0.5||e_k||^2 (4 independent FMA chains)
__device__ __forceinline__ float rescore(const float* __restrict__ embed,
                                          const float* __restrict__ sx,
                                          const float* __restrict__ shes,
                                          int p, int k) {
    const float4* er = (const float4*)(embed + (size_t)k * D);
    float s0 = 0.f, s1 = 0.f, s2 = 0.f, s3 = 0.f;
    #pragma unroll
    for (int i = 0; i < 16; i++) {
        float4 e4 = er[i];
        s0 = fmaf(sx[(4 * i + 0) * SXS + p], e4.x, s0);
        s1 = fmaf(sx[(4 * i + 1) * SXS + p], e4.y, s1);
        s2 = fmaf(sx[(4 * i + 2) * SXS + p], e4.z, s2);
        s3 = fmaf(sx[(4 * i + 3) * SXS + p], e4.w, s3);
    }
    return ((s0 + s1) + (s2 + s3)) - shes[k];
}

// ---------------- prep: hi split codebook (permuted+swizzled), half norms ----
// element d = 32g+16c+8h+2rr+par -> slot ((g<<2)+rr+((k&1)<<2))&7, idx (2c+h)*2+par
__global__ void vq_prep(const float* __restrict__ embed) {
    int k = blockIdx.x, d = threadIdx.x;
    float v = embed[k * D + d];
    __half a = __float2half_rn(v);
    int g = d >> 5, kk = d & 31;
    int rr = (kk >> 1) & 3, h = (kk >> 3) & 1, c = (kk >> 4) & 1, par = kk & 1;
    int slot = ((g << 2) + rr + ((k & 1) << 2)) & 7;
    g_ea[k * 64 + slot * 8 + ((c << 1) + h) * 2 + par] = a;
    float s = v * v;
    #pragma unroll
    for (int o = 16; o > 0; o >>= 1) s += __shfl_down_sync(0xffffffffu, s, o);
    __shared__ float ws[2];
    if ((d & 31) == 0) ws[d >> 5] = s;
    __syncthreads();
    if (d == 0) {
        float hes = 0.5f * (ws[0] + ws[1]);
        g_hes[k] = hes;
        atomicMax(&g_mhbits, __float_as_int(hes));
    }
}

// ---------------- main ----------------
__global__ void __launch_bounds__(T, 2) vq_main(const float* __restrict__ x,
                                                const float* __restrict__ embed,
                                                float* __restrict__ outq,
                                                float* __restrict__ outi) {
    extern __shared__ __align__(128) char smem[];
    uint32_t sb = smem_u32(smem);
    const int tid = threadIdx.x, wid = tid >> 5, lane = tid & 31;
    const int q = lane >> 2, r = lane & 3;
    const int wm = wid >> 1;                 // m-quarter (32 pixels, 2 m-tiles)
    const int ng = wid & 1;                  // n-half (256 codes, 32 tiles)
    const int n0 = blockIdx.x * MT;
    const int b = n0 >> 12, hw0 = n0 & 4095;

    float* sx = (float*)(smem + SX_OFF);     // [d][SXS]
    float* shes = (float*)(smem + SHES_OFF);
    unsigned* sapx = (unsigned*)(smem + SAPX_OFF);
    unsigned long long* sbest = (unsigned long long*)(smem + SBEST_OFF);

    // stage hi codebook (64KB) via cp.async
    #pragma unroll
    for (int t = 0; t < 16; t++) {
        int c = tid + t * T;                 // 4096 16B chunks
        cp16(sb + BA_OFF + c * 16, (const char*)g_ea + c * 16);
    }
    CP_COMMIT();

    // stage x tile: sx[c][j] = x[b][c][hw0+j] (padded stride SXS)
    #pragma unroll
    for (int t = 0; t < 8; t++) {
        int i = tid + t * T;
        int c = i >> 5, j4 = (i & 31) << 2;
        float4 v = *(const float4*)(x + (((size_t)(b * D + c)) << 12) + hw0 + j4);
        *(float4*)(sx + c * SXS + j4) = v;
    }
    shes[tid] = g_hes[tid];
    shes[tid + 256] = g_hes[tid + 256];
    if (tid < MT) { sapx[tid] = 0u; sbest[tid] = 0ull; }
    CP_WAIT(0);
    __syncthreads();

    // A hi fragments for 2 m-tiles + ||x||^2 partials (stay in registers)
    const int m0 = wm * 32;
    uint32_t Aa[2][4][4];
    float xp[4] = {0.f, 0.f, 0.f, 0.f};
    #pragma unroll
    for (int mt = 0; mt < 2; mt++) {
        #pragma unroll
        for (int cc = 0; cc < 4; cc++) {
            #pragma unroll
            for (int hh = 0; hh < 2; hh++) {
                int k = 16 * cc + 8 * hh + 2 * r;
                int r0 = m0 + mt * 16 + q;
                float f0a = sx[k * SXS + r0],     f1a = sx[(k + 1) * SXS + r0];
                float f0b = sx[k * SXS + r0 + 8], f1b = sx[(k + 1) * SXS + r0 + 8];
                xp[2 * mt]     = fmaf(f0a, f0a, fmaf(f1a, f1a, xp[2 * mt]));
                xp[2 * mt + 1] = fmaf(f0b, f0b, fmaf(f1b, f1b, xp[2 * mt + 1]));
                Aa[mt][cc][2 * hh]     = pack2(__float2half_rn(f0a), __float2half_rn(f1a));
                Aa[mt][cc][2 * hh + 1] = pack2(__float2half_rn(f0b), __float2half_rn(f1b));
            }
        }
    }
    #pragma unroll
    for (int i = 0; i < 4; i++) {
        xp[i] += __shfl_xor_sync(0xffffffffu, xp[i], 1);
        xp[i] += __shfl_xor_sync(0xffffffffu, xp[i], 2);
    }

    // ---- single screen pass: MMA + top-2 tracking per row-slice ----
    float best[4] = {-FLT_MAX, -FLT_MAX, -FLT_MAX, -FLT_MAX};
    float snd[4]  = {-FLT_MAX, -FLT_MAX, -FLT_MAX, -FLT_MAX};
    int bestk[4]  = {0, 0, 0, 0};

    #pragma unroll 1
    for (int G = 0; G < 8; G++) {
        float acc[2][4][4];
        #pragma unroll
        for (int mt = 0; mt < 2; mt++)
            #pragma unroll
            for (int j = 0; j < 4; j++)
                #pragma unroll
                for (int c = 0; c < 4; c++) acc[mt][j][c] = 0.f;
        #pragma unroll
        for (int j = 0; j < 4; j++) {
            int n = (ng * 32 + G * 4 + j) * 8 + q;
            const char* rowa = smem + BA_OFF + n * 128;
            int so = r + ((n & 1) << 2);
            uint4 v0 = *(const uint4*)(rowa + (so & 7) * 16);
            uint4 v1 = *(const uint4*)(rowa + ((so + 4) & 7) * 16);
            #pragma unroll
            for (int mt = 0; mt < 2; mt++) {
                MMA_F16(acc[mt][j], Aa[mt][0][0], Aa[mt][0][1], Aa[mt][0][2], Aa[mt][0][3], v0.x, v0.y);
                MMA_F16(acc[mt][j], Aa[mt][1][0], Aa[mt][1][1], Aa[mt][1][2], Aa[mt][1][3], v0.z, v0.w);
                MMA_F16(acc[mt][j], Aa[mt][2][0], Aa[mt][2][1], Aa[mt][2][2], Aa[mt][2][3], v1.x, v1.y);
                MMA_F16(acc[mt][j], Aa[mt][3][0], Aa[mt][3][1], Aa[mt][3][2], Aa[mt][3][3], v1.z, v1.w);
            }
        }
        #pragma unroll
        for (int j = 0; j < 4; j++) {
            int cb = (ng * 32 + G * 4 + j) * 8 + 2 * r;
            float h0 = shes[cb], h1 = shes[cb + 1];
            #pragma unroll
            for (int mt = 0; mt < 2; mt++) {
                #pragma unroll
                for (int half = 0; half < 2; half++) {
                    int i = 2 * mt + half;
                    float v0 = acc[mt][j][2 * half + 0] - h0;
                    float v1 = acc[mt][j][2 * half + 1] - h1;
                    // top-2 update with pairwise prereduce
                    float pm = fmaxf(v0, v1), pn = fminf(v0, v1);
                    int kp = (v0 >= v1) ? cb : cb + 1;
                    float s1n = fmaxf(snd[i], pn);
                    bool p = pm > best[i];
                    snd[i] = fmaxf(s1n, p ? best[i] : pm);
                    bestk[i] = p ? kp : bestk[i];
                    best[i] = fmaxf(best[i], pm);
                }
            }
        }
    }
    // publish per-row global approx max
    #pragma unroll
    for (int i = 0; i < 4; i++)
        atomicMax(&sapx[m0 + (i >> 1) * 16 + (i & 1) * 8 + q], ord_enc(best[i]));
    __syncthreads();

    // ---- certified exact resolution ----
    {
        float maxEn = sqrtf(2.0f * __int_as_float(g_mhbits));
        #pragma unroll
        for (int i = 0; i < 4; i++) {
            int row = m0 + (i >> 1) * 16 + (i & 1) * 8 + q;
            unsigned u = sapx[row];
            float smax = __uint_as_float((u & 0x80000000u) ? (u & 0x7fffffffu) : ~u);
            float thr = smax - (2.2e-3f * sqrtf(xp[i]) * maxEn + 1e-5f);
            if (best[i] >= thr) {
                if (snd[i] >= thr) {
                    // rare: >=2 candidates hide in this slice -> exact rescan of all 64
                    for (int G = 0; G < 8; G++) {
                        #pragma unroll
                        for (int j = 0; j < 4; j++) {
                            int cb = (ng * 32 + G * 4 + j) * 8 + 2 * r;
                            float s0 = rescore(embed, sx, shes, row, cb);
                            atomicMax(&sbest[row],
                                ((unsigned long long)ord_enc(s0) << 32) |
                                (unsigned)(K - 1 - cb));
                            float s1 = rescore(embed, sx, shes, row, cb + 1);
                            atomicMax(&sbest[row],
                                ((unsigned long long)ord_enc(s1) << 32) |
                                (unsigned)(K - 1 - (cb + 1)));
                        }
                    }
                } else {
                    float se = rescore(embed, sx, shes, row, bestk[i]);
                    atomicMax(&sbest[row],
                        ((unsigned long long)ord_enc(se) << 32) |
                        (unsigned)(K - 1 - bestk[i]));
                }
            }
        }
    }
    __syncthreads();

    // outputs: gathered codebook rows (NHWC) + indices (float)
    #pragma unroll
    for (int t = 0; t < 8; t++) {
        int i = tid + t * T;                      // MT*16 = 2048 float4 writes
        int j = i >> 4, c4 = i & 15;
        int idx = (K - 1) - (int)(sbest[j] & 0xffffffffull);
        float4 v = *(const float4*)(embed + idx * D + (c4 << 2));
        *(float4*)(outq + ((size_t)(n0 + j)) * D + (c4 << 2)) = v;
    }
    if (outi && tid < MT)
        outi[n0 + tid] = (float)((K - 1) - (int)(sbest[tid] & 0xffffffffull));
}

// ---------------------------------------------------------------------------
extern "C" void kernel_launch(void* const* d_in, const int* in_sizes, int n_in,
                              void* d_out, int out_size) {
    const float* x = (const float*)d_in[0];
    const float* embed = (const float*)d_in[1];
    float* out = (float*)d_out;

    const int N = in_sizes[0] / D;
    float* outi = nullptr;
    if (out_size >= N * D + N) outi = out + (size_t)N * D;

    cudaFuncSetAttribute(vq_main, cudaFuncAttributeMaxDynamicSharedMemorySize, SMEM_SZ);
    vq_prep<<<K, D>>>(embed);
    vq_main<<<N / MT, T, SMEM_SZ>>>(x, embed, out, outi);
}